// round 4
// baseline (speedup 1.0000x reference)
#include <cuda_runtime.h>
#include <cstdint>

// ---------------------------------------------------------------------------
// ChainGNN: 3-layer GAT (heads 4/2/1, ch 32/32/16), N=50000, E=800000 (+self loops)
// NOTE: edge_index arrives as int32 (JAX x64 disabled downgrades jnp.int64).
// ---------------------------------------------------------------------------

constexpr int NN = 50000;
constexpr int EMAX = 800000;
constexpr float SLOPE = 0.2f;

// Scratch (device globals; allocation is forbidden)
__device__ float g_h[NN * 128];     // post-GEMM features of current layer
__device__ float g_acc[NN * 128];   // aggregation accumulator
__device__ float g_y1[NN * 128];    // layer1 activations
__device__ float g_y2[NN * 64];     // layer2 activations
__device__ float g_as[NN * 4];
__device__ float g_ad[NN * 4];
__device__ float g_m[NN * 4];
__device__ float g_den[NN * 4];
__device__ float g_inv[NN * 4];
__device__ float g_e[EMAX * 4];     // per-edge logits, then exp values

__device__ __forceinline__ float leaky(float v) { return v > 0.f ? v : SLOPE * v; }

__device__ __forceinline__ void atomicMaxFloat(float* addr, float value) {
    if (value >= 0.f) atomicMax((int*)addr, __float_as_int(value));
    else              atomicMin((unsigned int*)addr, __float_as_uint(value));
}

__device__ __forceinline__ void red_add_v4(float* p, float a, float b, float c, float d) {
    asm volatile("red.global.add.v4.f32 [%0], {%1, %2, %3, %4};"
                 :: "l"(p), "f"(a), "f"(b), "f"(c), "f"(d) : "memory");
}
__device__ __forceinline__ void red_add_v2(float* p, float a, float b) {
    asm volatile("red.global.add.v2.f32 [%0], {%1, %2};"
                 :: "l"(p), "f"(a), "f"(b) : "memory");
}

// ---------------------------------------------------------------------------
// GEMM: O[n, outc] = X[n, K] @ W[K, outc].  64x64 tile, 4x4 per thread.
// ---------------------------------------------------------------------------
__global__ void gemm_kernel(const float* __restrict__ X, const float* __restrict__ W,
                            float* __restrict__ O, int n, int K, int outc) {
    constexpr int BM = 64, BN = 64, BK = 16, TM = 4, TN = 4;
    __shared__ float Xs[BM][BK];
    __shared__ float Ws[BK][BN];
    int t = threadIdx.x;               // 256 threads
    int row0 = blockIdx.y * BM;
    int col0 = blockIdx.x * BN;
    int tidx = t & 15, tidy = t >> 4;
    float acc[TM][TN] = {};

    for (int kk = 0; kk < K; kk += BK) {
        // load X tile: thread t -> row t/4, 4 floats at (t%4)*4
        {
            int r = t >> 2;
            int seg = (t & 3) * 4;
            int grow = row0 + r;
            float4 xv = make_float4(0.f, 0.f, 0.f, 0.f);
            if (grow < n)
                xv = *reinterpret_cast<const float4*>(&X[(size_t)grow * K + kk + seg]);
            *reinterpret_cast<float4*>(&Xs[r][seg]) = xv;
        }
        // load W tile: thread t -> row t/16, 4 floats at (t%16)*4
        {
            int wr = t >> 4;
            int wc = (t & 15) * 4;
            int gcol = col0 + wc;
            float4 wv = make_float4(0.f, 0.f, 0.f, 0.f);
            if (gcol < outc)
                wv = *reinterpret_cast<const float4*>(&W[(size_t)(kk + wr) * outc + gcol]);
            *reinterpret_cast<float4*>(&Ws[wr][wc]) = wv;  // zeros if out of range
        }
        __syncthreads();
        #pragma unroll
        for (int k = 0; k < BK; k++) {
            float rm[TM];
            #pragma unroll
            for (int i = 0; i < TM; i++) rm[i] = Xs[tidy * TM + i][k];
            float4 rn4 = *reinterpret_cast<const float4*>(&Ws[k][tidx * TN]);
            float rn[TN] = {rn4.x, rn4.y, rn4.z, rn4.w};
            #pragma unroll
            for (int i = 0; i < TM; i++)
                #pragma unroll
                for (int j = 0; j < TN; j++) acc[i][j] += rm[i] * rn[j];
        }
        __syncthreads();
    }
    #pragma unroll
    for (int i = 0; i < TM; i++) {
        int gr = row0 + tidy * TM + i;
        if (gr >= n) continue;
        int gc = col0 + tidx * TN;
        if (gc < outc)
            *reinterpret_cast<float4*>(&O[(size_t)gr * outc + gc]) =
                make_float4(acc[i][0], acc[i][1], acc[i][2], acc[i][3]);
    }
}

// ---------------------------------------------------------------------------
// Per-node attention scalars: as = <h, a_src>, ad = <h, a_dst>, m init = self logit
// One warp per node.
// ---------------------------------------------------------------------------
template <int H, int C>
__global__ void attn_node_kernel(const float* __restrict__ h,
                                 const float* __restrict__ a_src,
                                 const float* __restrict__ a_dst,
                                 float* __restrict__ as_, float* __restrict__ ad_,
                                 float* __restrict__ m_, float* __restrict__ den_) {
    int node = blockIdx.x * (blockDim.x >> 5) + (threadIdx.x >> 5);
    if (node >= NN) return;
    int lane = threadIdx.x & 31;
    const float* hr = h + (size_t)node * H * C;
    #pragma unroll
    for (int hh = 0; hh < H; hh++) {
        float s = 0.f, d = 0.f;
        for (int c = lane; c < C; c += 32) {
            float v = hr[hh * C + c];
            s += v * a_src[hh * C + c];
            d += v * a_dst[hh * C + c];
        }
        #pragma unroll
        for (int o = 16; o > 0; o >>= 1) {
            s += __shfl_xor_sync(0xffffffffu, s, o);
            d += __shfl_xor_sync(0xffffffffu, d, o);
        }
        if (lane == 0) {
            as_[node * H + hh] = s;
            ad_[node * H + hh] = d;
            m_[node * H + hh] = leaky(s + d);   // self-loop logit seeds the max
            den_[node * H + hh] = 0.f;
        }
    }
}

// ---------------------------------------------------------------------------
// Edge pass 1: logits + segment max
// ---------------------------------------------------------------------------
template <int H>
__global__ void edge_logit_kernel(const int* __restrict__ ei, int E,
                                  const float* __restrict__ as_,
                                  const float* __restrict__ ad_,
                                  float* __restrict__ logit, float* __restrict__ m_) {
    int e = blockIdx.x * blockDim.x + threadIdx.x;
    if (e >= E) return;
    int s = ei[e], d = ei[E + e];
    #pragma unroll
    for (int hh = 0; hh < H; hh++) {
        float l = leaky(as_[s * H + hh] + ad_[d * H + hh]);
        logit[(size_t)e * H + hh] = l;
        atomicMaxFloat(&m_[d * H + hh], l);
    }
}

// ---------------------------------------------------------------------------
// Edge pass 2: e = exp(logit - m[dst]); denom[dst] += e
// ---------------------------------------------------------------------------
template <int H>
__global__ void edge_exp_kernel(const int* __restrict__ ei, int E,
                                float* __restrict__ logit, const float* __restrict__ m_,
                                float* __restrict__ den_) {
    int e = blockIdx.x * blockDim.x + threadIdx.x;
    if (e >= E) return;
    int d = ei[E + e];
    float ev[H];
    #pragma unroll
    for (int hh = 0; hh < H; hh++) {
        float x = __expf(logit[(size_t)e * H + hh] - m_[d * H + hh]);
        logit[(size_t)e * H + hh] = x;
        ev[hh] = x;
    }
    if constexpr (H == 4)      red_add_v4(&den_[d * 4], ev[0], ev[1], ev[2], ev[3]);
    else if constexpr (H == 2) red_add_v2(&den_[d * 2], ev[0], ev[1]);
    else                       atomicAdd(&den_[d], ev[0]);
}

// ---------------------------------------------------------------------------
// Node pass: finish denominator with self term, compute 1/denom,
// initialize accumulator with the self-loop message. One warp per node.
// ---------------------------------------------------------------------------
template <int H, int C>
__global__ void node_self_kernel(const float* __restrict__ h,
                                 const float* __restrict__ as_, const float* __restrict__ ad_,
                                 const float* __restrict__ m_, const float* __restrict__ den_,
                                 float* __restrict__ inv_, float* __restrict__ acc) {
    int node = blockIdx.x * (blockDim.x >> 5) + (threadIdx.x >> 5);
    if (node >= NN) return;
    int lane = threadIdx.x & 31;
    float coef = 0.f;
    if (lane < H) {
        float l = leaky(as_[node * H + lane] + ad_[node * H + lane]);
        float es = __expf(l - m_[node * H + lane]);
        float dd = den_[node * H + lane] + es;
        float iv = 1.f / (dd + 1e-16f);
        inv_[node * H + lane] = iv;
        coef = es * iv;   // self-loop attention weight
    }
    const float* hr = h + (size_t)node * H * C;
    float* ar = acc + (size_t)node * H * C;
    constexpr int NV4 = H * C / 4;
    for (int q = lane; q < NV4; q += 32) {
        int hh = (q * 4) / C;
        float cf = __shfl_sync(0xffffffffu, coef, hh);
        float4 hv = *reinterpret_cast<const float4*>(&hr[q * 4]);
        *reinterpret_cast<float4*>(&ar[q * 4]) =
            make_float4(hv.x * cf, hv.y * cf, hv.z * cf, hv.w * cf);
    }
}

// ---------------------------------------------------------------------------
// Edge pass 3: acc[dst] += h[src] * (e * inv[dst]).  H*C/4 lanes per edge,
// each lane does a coalesced float4 gather + one vector RED.
// ---------------------------------------------------------------------------
template <int H, int C>
__global__ void edge_scatter_kernel(const int* __restrict__ ei, int E,
                                    const float* __restrict__ h,
                                    const float* __restrict__ ebuf,
                                    const float* __restrict__ inv_,
                                    float* __restrict__ acc) {
    constexpr int LPE = H * C / 4;
    int t = blockIdx.x * blockDim.x + threadIdx.x;
    int e = t / LPE;
    int sub = t % LPE;
    if (e >= E) return;
    int s = ei[e], d = ei[E + e];
    int idx = sub * 4;
    int hh = idx / C;
    float coef = ebuf[(size_t)e * H + hh] * inv_[d * H + hh];
    float4 hv = *reinterpret_cast<const float4*>(&h[(size_t)s * H * C + idx]);
    red_add_v4(&acc[(size_t)d * H * C + idx],
               hv.x * coef, hv.y * coef, hv.z * coef, hv.w * coef);
}

// ---------------------------------------------------------------------------
// Finalize: y = (acc + bias) [relu]
// ---------------------------------------------------------------------------
__global__ void finalize_kernel(const float* __restrict__ acc, const float* __restrict__ bias,
                                float* __restrict__ y, int total, int OC, int do_relu) {
    int i = blockIdx.x * blockDim.x + threadIdx.x;
    if (i >= total) return;
    float v = acc[i] + bias[i % OC];
    if (do_relu) v = v > 0.f ? v : 0.f;
    y[i] = v;
}

// ---------------------------------------------------------------------------
// Launch
// ---------------------------------------------------------------------------
template <int H, int C>
static void run_layer(const float* x, int K, const int* ei, int E,
                      const float* W, const float* asrc, const float* adst, const float* bias,
                      float* h, float* acc, float* pas, float* pad, float* pm,
                      float* pden, float* pinv, float* pe,
                      float* y, int do_relu) {
    constexpr int OC = H * C;
    dim3 ggrid((OC + 63) / 64, (NN + 63) / 64);
    gemm_kernel<<<ggrid, 256>>>(x, W, h, NN, K, OC);
    attn_node_kernel<H, C><<<(NN + 3) / 4, 128>>>(h, asrc, adst, pas, pad, pm, pden);
    edge_logit_kernel<H><<<(E + 255) / 256, 256>>>(ei, E, pas, pad, pe, pm);
    edge_exp_kernel<H><<<(E + 255) / 256, 256>>>(ei, E, pe, pm, pden);
    node_self_kernel<H, C><<<(NN + 3) / 4, 128>>>(h, pas, pad, pm, pden, pinv, acc);
    constexpr int LPE = H * C / 4;
    long long nthr = (long long)E * LPE;
    edge_scatter_kernel<H, C><<<(unsigned)((nthr + 255) / 256), 256>>>(ei, E, h, pe, pinv, acc);
    finalize_kernel<<<(NN * OC + 255) / 256, 256>>>(acc, bias, y, NN * OC, OC, do_relu);
}

extern "C" void kernel_launch(void* const* d_in, const int* in_sizes, int n_in,
                              void* d_out, int out_size) {
    const float* x = (const float*)d_in[0];
    const int* ei = (const int*)d_in[1];           // int32! (JAX x64 disabled)
    const float* W1 = (const float*)d_in[2];
    const float* as1 = (const float*)d_in[3];
    const float* ad1 = (const float*)d_in[4];
    const float* b1 = (const float*)d_in[5];
    const float* W2 = (const float*)d_in[6];
    const float* as2 = (const float*)d_in[7];
    const float* ad2 = (const float*)d_in[8];
    const float* b2 = (const float*)d_in[9];
    const float* W3 = (const float*)d_in[10];
    const float* as3 = (const float*)d_in[11];
    const float* ad3 = (const float*)d_in[12];
    const float* b3 = (const float*)d_in[13];
    int E = in_sizes[1] / 2;

    float *h, *acc, *y1, *y2, *pas, *pad, *pm, *pden, *pinv, *pe;
    cudaGetSymbolAddress((void**)&h, g_h);
    cudaGetSymbolAddress((void**)&acc, g_acc);
    cudaGetSymbolAddress((void**)&y1, g_y1);
    cudaGetSymbolAddress((void**)&y2, g_y2);
    cudaGetSymbolAddress((void**)&pas, g_as);
    cudaGetSymbolAddress((void**)&pad, g_ad);
    cudaGetSymbolAddress((void**)&pm, g_m);
    cudaGetSymbolAddress((void**)&pden, g_den);
    cudaGetSymbolAddress((void**)&pinv, g_inv);
    cudaGetSymbolAddress((void**)&pe, g_e);

    // Layer 1: in 128 -> 4 heads x 32, concat (128), relu
    run_layer<4, 32>(x, 128, ei, E, W1, as1, ad1, b1,
                     h, acc, pas, pad, pm, pden, pinv, pe, y1, 1);
    // Layer 2: in 128 -> 2 heads x 32, concat (64), relu
    run_layer<2, 32>(y1, 128, ei, E, W2, as2, ad2, b2,
                     h, acc, pas, pad, pm, pden, pinv, pe, y2, 1);
    // Layer 3: in 64 -> 1 head x 16, mean == identity, no relu -> output
    run_layer<1, 16>(y2, 64, ei, E, W3, as3, ad3, b3,
                     h, acc, pas, pad, pm, pden, pinv, pe, (float*)d_out, 0);
}

// round 6
// speedup vs baseline: 1.3684x; 1.3684x over previous
#include <cuda_runtime.h>
#include <cstdint>

// ---------------------------------------------------------------------------
// ChainGNN: 3-layer GAT (heads 4/2/1, ch 32/32/16), N=50000, E=800000 (+self loops)
// CSR-fused design: build group-by-dst CSR once, then one fused
// online-softmax aggregation kernel per layer (no atomics in hot path).
// ---------------------------------------------------------------------------

constexpr int NN = 50000;
constexpr int EMAX = 800000;
constexpr float SLOPE = 0.2f;

// Scratch (device globals; allocation is forbidden)
__device__ float g_h[NN * 128];       // post-GEMM features of current layer
__device__ float g_y1[NN * 128];      // layer1 activations
__device__ float g_y2[NN * 64];       // layer2 activations
__device__ float g_as[NN * 4];
__device__ float g_ad[NN * 4];
__device__ int   g_cnt[NN];
__device__ int   g_off[NN + 1];
__device__ int   g_cursor[NN];
__device__ int   g_csr_src[EMAX];

__device__ __forceinline__ float leaky(float v) { return v > 0.f ? v : SLOPE * v; }

// ---------------------------------------------------------------------------
// GEMM: O[n, outc] = X[n, K] @ W[K, outc].  128x64 tile, 8x4 per thread.
// ---------------------------------------------------------------------------
__global__ void gemm_kernel(const float* __restrict__ X, const float* __restrict__ W,
                            float* __restrict__ O, int n, int K, int outc) {
    constexpr int BM = 128, BN = 64, BK = 16, TM = 8, TN = 4;
    __shared__ float Xs[BM][BK];
    __shared__ float Ws[BK][BN];
    int t = threadIdx.x;               // 256 threads
    int row0 = blockIdx.y * BM;
    int col0 = blockIdx.x * BN;
    int tidx = t & 15, tidy = t >> 4;
    float acc[TM][TN] = {};

    for (int kk = 0; kk < K; kk += BK) {
        // load X tile: 512 float4s, 2 per thread
        #pragma unroll
        for (int j = 0; j < 2; j++) {
            int f = t * 2 + j;
            int r = f >> 2;
            int seg = (f & 3) * 4;
            int grow = row0 + r;
            float4 xv = make_float4(0.f, 0.f, 0.f, 0.f);
            if (grow < n)
                xv = *reinterpret_cast<const float4*>(&X[(size_t)grow * K + kk + seg]);
            *reinterpret_cast<float4*>(&Xs[r][seg]) = xv;
        }
        // load W tile: 256 float4s, 1 per thread
        {
            int wr = t >> 4;
            int wc = (t & 15) * 4;
            int gcol = col0 + wc;
            float4 wv = make_float4(0.f, 0.f, 0.f, 0.f);
            if (gcol < outc)
                wv = *reinterpret_cast<const float4*>(&W[(size_t)(kk + wr) * outc + gcol]);
            *reinterpret_cast<float4*>(&Ws[wr][wc]) = wv;  // zeros if out of range
        }
        __syncthreads();
        #pragma unroll
        for (int k = 0; k < BK; k++) {
            float rm[TM];
            #pragma unroll
            for (int i = 0; i < TM; i++) rm[i] = Xs[tidy * TM + i][k];
            float4 rn4 = *reinterpret_cast<const float4*>(&Ws[k][tidx * TN]);
            float rn[TN] = {rn4.x, rn4.y, rn4.z, rn4.w};
            #pragma unroll
            for (int i = 0; i < TM; i++)
                #pragma unroll
                for (int j = 0; j < TN; j++) acc[i][j] += rm[i] * rn[j];
        }
        __syncthreads();
    }
    #pragma unroll
    for (int i = 0; i < TM; i++) {
        int gr = row0 + tidy * TM + i;
        if (gr >= n) continue;
        int gc = col0 + tidx * TN;
        if (gc < outc)
            *reinterpret_cast<float4*>(&O[(size_t)gr * outc + gc]) =
                make_float4(acc[i][0], acc[i][1], acc[i][2], acc[i][3]);
    }
}

// ---------------------------------------------------------------------------
// CSR build: histogram -> scan -> scatter
// ---------------------------------------------------------------------------
__global__ void zero_cnt_kernel(int* __restrict__ cnt) {
    int i = blockIdx.x * blockDim.x + threadIdx.x;
    if (i < NN) cnt[i] = 0;
}

__global__ void hist_kernel(const int* __restrict__ ei, int E, int* __restrict__ cnt) {
    int e = blockIdx.x * blockDim.x + threadIdx.x;
    if (e < E) atomicAdd(&cnt[ei[E + e]], 1);
}

// single-block exclusive scan over NN counters
__global__ void scan_kernel(const int* __restrict__ cnt, int* __restrict__ off,
                            int* __restrict__ cursor) {
    __shared__ int part[1024];
    int t = threadIdx.x;
    constexpr int PER = (NN + 1023) / 1024;   // 49
    int base = t * PER;
    int sum = 0;
    for (int i = 0; i < PER; i++) {
        int idx = base + i;
        sum += (idx < NN) ? cnt[idx] : 0;
    }
    part[t] = sum;
    __syncthreads();
    // inclusive Hillis-Steele scan
    for (int o = 1; o < 1024; o <<= 1) {
        int other = (t >= o) ? part[t - o] : 0;
        __syncthreads();
        part[t] += other;
        __syncthreads();
    }
    int run = part[t] - sum;   // exclusive chunk offset
    for (int i = 0; i < PER; i++) {
        int idx = base + i;
        if (idx < NN) {
            off[idx] = run;
            cursor[idx] = run;
            run += cnt[idx];
        }
    }
    if (t == 1023) off[NN] = part[1023];
}

__global__ void build_kernel(const int* __restrict__ ei, int E,
                             int* __restrict__ cursor, int* __restrict__ csr_src) {
    int e = blockIdx.x * blockDim.x + threadIdx.x;
    if (e >= E) return;
    int d = ei[E + e];
    int pos = atomicAdd(&cursor[d], 1);
    csr_src[pos] = ei[e];
}

// ---------------------------------------------------------------------------
// Per-node attention scalars: as = <h, a_src>, ad = <h, a_dst>. One warp/node.
// ---------------------------------------------------------------------------
template <int H, int C>
__global__ void attn_node_kernel(const float* __restrict__ h,
                                 const float* __restrict__ a_src,
                                 const float* __restrict__ a_dst,
                                 float* __restrict__ as_, float* __restrict__ ad_) {
    int node = blockIdx.x * (blockDim.x >> 5) + (threadIdx.x >> 5);
    if (node >= NN) return;
    int lane = threadIdx.x & 31;
    const float* hr = h + (size_t)node * H * C;
    #pragma unroll
    for (int hh = 0; hh < H; hh++) {
        float s = 0.f, d = 0.f;
        for (int c = lane; c < C; c += 32) {
            float v = hr[hh * C + c];
            s += v * a_src[hh * C + c];
            d += v * a_dst[hh * C + c];
        }
        #pragma unroll
        for (int o = 16; o > 0; o >>= 1) {
            s += __shfl_xor_sync(0xffffffffu, s, o);
            d += __shfl_xor_sync(0xffffffffu, d, o);
        }
        if (lane == 0) {
            as_[node * H + hh] = s;
            ad_[node * H + hh] = d;
        }
    }
}

// ---------------------------------------------------------------------------
// Fused aggregation: per dst node, online-softmax over its in-edges + self loop.
// H*C/4 lanes per node, each owns a float4 slice. No atomics, all in registers.
// Epilogue applies bias (+relu). Mean over 1 head (layer 3) == identity.
// ---------------------------------------------------------------------------
template <int H, int C, int RELU>
__global__ void aggregate_kernel(const int* __restrict__ off,
                                 const int* __restrict__ csr_src,
                                 const float* __restrict__ h,
                                 const float* __restrict__ as_,
                                 const float* __restrict__ ad_,
                                 const float* __restrict__ bias,
                                 float* __restrict__ y) {
    constexpr int HC = H * C;
    constexpr int LPN = HC / 4;         // lanes per node
    constexpr int NPB = 128 / LPN;      // nodes per 128-thread block
    int t = threadIdx.x;
    int sub = t % LPN;
    int node = blockIdx.x * NPB + t / LPN;
    if (node >= NN) return;

    int fo = sub * 4;
    int hh = fo / C;
    float ad_d = ad_[node * H + hh];

    // self loop seeds the online softmax
    float m = leaky(as_[node * H + hh] + ad_d);
    float den = 1.f;
    float4 acc = *reinterpret_cast<const float4*>(&h[(size_t)node * HC + fo]);

    int beg = off[node], end = off[node + 1];
    for (int idx = beg; idx < end; idx++) {
        int s = csr_src[idx];
        float l = leaky(as_[s * H + hh] + ad_d);
        float4 hv = *reinterpret_cast<const float4*>(&h[(size_t)s * HC + fo]);
        float nm = fmaxf(m, l);
        float scale = __expf(m - nm);
        float p = __expf(l - nm);
        acc.x = acc.x * scale + p * hv.x;
        acc.y = acc.y * scale + p * hv.y;
        acc.z = acc.z * scale + p * hv.z;
        acc.w = acc.w * scale + p * hv.w;
        den = den * scale + p;
        m = nm;
    }

    float iv = 1.f / (den + 1e-16f);
    float4 bv = *reinterpret_cast<const float4*>(&bias[fo]);
    float4 o;
    o.x = acc.x * iv + bv.x;
    o.y = acc.y * iv + bv.y;
    o.z = acc.z * iv + bv.z;
    o.w = acc.w * iv + bv.w;
    if (RELU) {
        o.x = fmaxf(o.x, 0.f); o.y = fmaxf(o.y, 0.f);
        o.z = fmaxf(o.z, 0.f); o.w = fmaxf(o.w, 0.f);
    }
    *reinterpret_cast<float4*>(&y[(size_t)node * HC + fo]) = o;
}

// ---------------------------------------------------------------------------
// Launch
// ---------------------------------------------------------------------------
template <int H, int C, int RELU>
static void run_layer(const float* x, int K,
                      const float* W, const float* asrc, const float* adst, const float* bias,
                      float* h, float* pas, float* pad,
                      const int* off, const int* csr_src, float* y) {
    constexpr int OC = H * C;
    dim3 ggrid((OC + 63) / 64, (NN + 127) / 128);
    gemm_kernel<<<ggrid, 256>>>(x, W, h, NN, K, OC);
    attn_node_kernel<H, C><<<(NN + 3) / 4, 128>>>(h, asrc, adst, pas, pad);
    constexpr int NPB = 128 / (OC / 4);
    aggregate_kernel<H, C, RELU><<<(NN + NPB - 1) / NPB, 128>>>(
        off, csr_src, h, pas, pad, bias, y);
}

extern "C" void kernel_launch(void* const* d_in, const int* in_sizes, int n_in,
                              void* d_out, int out_size) {
    const float* x = (const float*)d_in[0];
    const int* ei = (const int*)d_in[1];           // int32 (JAX x64 disabled)
    const float* W1 = (const float*)d_in[2];
    const float* as1 = (const float*)d_in[3];
    const float* ad1 = (const float*)d_in[4];
    const float* b1 = (const float*)d_in[5];
    const float* W2 = (const float*)d_in[6];
    const float* as2 = (const float*)d_in[7];
    const float* ad2 = (const float*)d_in[8];
    const float* b2 = (const float*)d_in[9];
    const float* W3 = (const float*)d_in[10];
    const float* as3 = (const float*)d_in[11];
    const float* ad3 = (const float*)d_in[12];
    const float* b3 = (const float*)d_in[13];
    int E = in_sizes[1] / 2;

    float *h, *y1, *y2, *pas, *pad;
    int *cnt, *off, *cursor, *csr_src;
    cudaGetSymbolAddress((void**)&h, g_h);
    cudaGetSymbolAddress((void**)&y1, g_y1);
    cudaGetSymbolAddress((void**)&y2, g_y2);
    cudaGetSymbolAddress((void**)&pas, g_as);
    cudaGetSymbolAddress((void**)&pad, g_ad);
    cudaGetSymbolAddress((void**)&cnt, g_cnt);
    cudaGetSymbolAddress((void**)&off, g_off);
    cudaGetSymbolAddress((void**)&cursor, g_cursor);
    cudaGetSymbolAddress((void**)&csr_src, g_csr_src);

    // Build CSR (group edges by destination) once; reused by all 3 layers.
    zero_cnt_kernel<<<(NN + 255) / 256, 256>>>(cnt);
    hist_kernel<<<(E + 255) / 256, 256>>>(ei, E, cnt);
    scan_kernel<<<1, 1024>>>(cnt, off, cursor);
    build_kernel<<<(E + 255) / 256, 256>>>(ei, E, cursor, csr_src);

    // Layer 1: in 128 -> 4 heads x 32, concat (128), relu
    run_layer<4, 32, 1>(x, 128, W1, as1, ad1, b1, h, pas, pad, off, csr_src, y1);
    // Layer 2: in 128 -> 2 heads x 32, concat (64), relu
    run_layer<2, 32, 1>(y1, 128, W2, as2, ad2, b2, h, pas, pad, off, csr_src, y2);
    // Layer 3: in 64 -> 1 head x 16, mean over 1 head == identity, no relu
    run_layer<1, 16, 0>(y2, 64, W3, as3, ad3, b3, h, pas, pad, off, csr_src, (float*)d_out);
}